// round 7
// baseline (speedup 1.0000x reference)
#include <cuda_runtime.h>
#include <cuda_fp16.h>
#include <cstdint>

// Covariance pooling: y[b] = (1/M) X Xᵀ - μ μᵀ, X = x[b] as [C=128, M=4096].
// fp16 m16n8k16 mma.sync path (same 10-bit mantissa as tf32, 2x FLOP per HMMA
// instruction -> halves the per-SMSP MMA-issue wall measured in R3-R5).
// Single kernel: 128 CTAs = 64 batches x 2 output row-slabs (64 rows), all
// resident in one wave; the 2 CTAs of a batch share x[b] via L2. 128 threads:
// each thread streams one of the 128 rows (LDG fp32 -> exact fp32 row sum ->
// rn-pack fp16 -> STS), double-buffered SMEM, one __syncthreads per k-tile.
// 4 warps in 2x2 over the 64x128 slab (warp tile 32x64). Mean subtraction
// applied in-kernel; direct stores to y. No scratch, no second kernel.

#define DINLINE __device__ __forceinline__

static constexpr int Bn = 64;
static constexpr int Cn = 128;
static constexpr int Mn = 4096;
static constexpr int KT = 64;              // k floats per tile
static constexpr int NKT = Mn / KT;        // 64
static constexpr int ROWB = 144;           // bytes per SMEM row: 128B fp16 + 16B pad
static constexpr int STAGE = Cn * ROWB;    // 18432

DINLINE void mma_f16(float d[4], const uint32_t a[4], uint32_t b0, uint32_t b1) {
    asm volatile(
        "mma.sync.aligned.m16n8k16.row.col.f32.f16.f16.f32 "
        "{%0,%1,%2,%3}, {%4,%5,%6,%7}, {%8,%9}, {%0,%1,%2,%3};"
        : "+f"(d[0]), "+f"(d[1]), "+f"(d[2]), "+f"(d[3])
        : "r"(a[0]), "r"(a[1]), "r"(a[2]), "r"(a[3]), "r"(b0), "r"(b1));
}
DINLINE void ldsm_x4(uint32_t r[4], uint32_t addr) {
    asm volatile("ldmatrix.sync.aligned.m8n8.x4.shared.b16 {%0,%1,%2,%3}, [%4];"
                 : "=r"(r[0]), "=r"(r[1]), "=r"(r[2]), "=r"(r[3]) : "r"(addr));
}
DINLINE uint32_t smem_u32(const void* p) {
    uint32_t a;
    asm("{ .reg .u64 t; cvta.to.shared.u64 t, %1; cvt.u32.u64 %0, t; }"
        : "=r"(a) : "l"(p));
    return a;
}

__global__ __launch_bounds__(128, 1)
void covpool_fp16(const float* __restrict__ x, float* __restrict__ y) {
    __shared__ __align__(16) char buf[2][STAGE];
    __shared__ float mu[Cn];

    const int t    = threadIdx.x;
    const int warp = t >> 5;
    const int lane = t & 31;
    const int s    = blockIdx.x & 1;      // output row-slab
    const int b    = blockIdx.x >> 1;

    // loader: one full row per thread
    const float* src = x + (size_t)b * Cn * Mn + (size_t)t * Mn;

    // warp tile 32(m) x 64(n) over the 64x128 slab
    const int wmL = s * 64 + (warp & 1) * 32;  // A row base (global C row)
    const int wn  = (warp >> 1) * 64;          // B row base (output col)
    const uint32_t base0 = smem_u32(buf[0]);
    const uint32_t base1 = smem_u32(buf[1]);
    const uint32_t aoff = (uint32_t)((wmL + (lane & 15)) * ROWB + (lane >> 4) * 16);
    const uint32_t boff = (uint32_t)((wn  + (lane & 15)) * ROWB + (lane >> 4) * 16);
    const int g  = lane >> 2;
    const int tg = lane & 3;

    float acc[2][8][4];
#pragma unroll
    for (int mi = 0; mi < 2; mi++)
#pragma unroll
        for (int in = 0; in < 8; in++)
#pragma unroll
            for (int j = 0; j < 4; j++) acc[mi][in][j] = 0.0f;

    float rs = 0.0f;
    uint32_t P[32];                            // packed fp16x2 staging (next tile)

    // prologue: load + convert tile 0
#pragma unroll
    for (int i = 0; i < 16; i++) {
        float4 v = __ldg((const float4*)(src + i * 4));
        rs += v.x + v.y + v.z + v.w;
        __half2 h0 = __floats2half2_rn(v.x, v.y);
        __half2 h1 = __floats2half2_rn(v.z, v.w);
        P[2 * i]     = *(const uint32_t*)&h0;
        P[2 * i + 1] = *(const uint32_t*)&h1;
    }

    for (int kt = 0; kt < NKT; kt++) {
        // STS packed tile into buf[kt&1]
        {
            char* d = buf[kt & 1] + t * ROWB;
#pragma unroll
            for (int i = 0; i < 8; i++)
                *(uint4*)(d + i * 16) =
                    make_uint4(P[4 * i], P[4 * i + 1], P[4 * i + 2], P[4 * i + 3]);
        }
        __syncthreads();

        // prefetch + convert tile kt+1 (overlaps MMA section below)
        if (kt + 1 < NKT) {
            const float* ns = src + (size_t)(kt + 1) * KT;
#pragma unroll
            for (int i = 0; i < 16; i++) {
                float4 v = __ldg((const float4*)(ns + i * 4));
                rs += v.x + v.y + v.z + v.w;
                __half2 h0 = __floats2half2_rn(v.x, v.y);
                __half2 h1 = __floats2half2_rn(v.z, v.w);
                P[2 * i]     = *(const uint32_t*)&h0;
                P[2 * i + 1] = *(const uint32_t*)&h1;
            }
        }

        // MMAs on buf[kt&1]
        const uint32_t base = (kt & 1) ? base1 : base0;
#pragma unroll
        for (int kc = 0; kc < 4; kc++) {
            const uint32_t k0 = (uint32_t)(kc * 32);   // 16 fp16 = 32 bytes
            uint32_t A[2][4], Bf[4][4];
            ldsm_x4(A[0], base + aoff + k0);
            ldsm_x4(A[1], base + aoff + 16 * ROWB + k0);
#pragma unroll
            for (int j = 0; j < 4; j++)
                ldsm_x4(Bf[j], base + boff + j * 16 * ROWB + k0);
#pragma unroll
            for (int mi = 0; mi < 2; mi++)
#pragma unroll
                for (int j = 0; j < 4; j++) {
                    mma_f16(acc[mi][2 * j],     A[mi], Bf[j][0], Bf[j][2]);
                    mma_f16(acc[mi][2 * j + 1], A[mi], Bf[j][1], Bf[j][3]);
                }
        }
        __syncthreads();
    }

    // means (exact fp32): thread t holds full-K sum of row t
    mu[t] = rs * (1.0f / (float)Mn);
    __syncthreads();

    // epilogue: y = acc/M - mu_r * mu_c, direct stores
    const float a = 1.0f / (float)Mn;
    float* yb = y + (size_t)b * Cn * Cn;
#pragma unroll
    for (int mi = 0; mi < 2; mi++) {
        const int r0 = wmL + mi * 16 + g;
        const float mr0 = mu[r0];
        const float mr1 = mu[r0 + 8];
#pragma unroll
        for (int in = 0; in < 8; in++) {
            const int c0 = wn + in * 8 + 2 * tg;
            const float mc0 = mu[c0];
            const float mc1 = mu[c0 + 1];
            float2 o0, o1;
            o0.x = acc[mi][in][0] * a - mr0 * mc0;
            o0.y = acc[mi][in][1] * a - mr0 * mc1;
            o1.x = acc[mi][in][2] * a - mr1 * mc0;
            o1.y = acc[mi][in][3] * a - mr1 * mc1;
            *(float2*)(yb + (size_t)r0 * Cn + c0)       = o0;
            *(float2*)(yb + (size_t)(r0 + 8) * Cn + c0) = o1;
        }
    }
}

extern "C" void kernel_launch(void* const* d_in, const int* in_sizes, int n_in,
                              void* d_out, int out_size) {
    (void)in_sizes; (void)n_in; (void)out_size;
    const float* x = (const float*)d_in[0];
    float* y = (float*)d_out;
    covpool_fp16<<<2 * Bn, 128>>>(x, y);
}

// round 9
// speedup vs baseline: 1.2450x; 1.2450x over previous
#include <cuda_runtime.h>
#include <cuda_fp16.h>
#include <cstdint>

// Covariance pooling: y[b] = (1/M) X Xᵀ - μ μᵀ, X = x[b] as [C=128, M=4096].
// fp16 m16n8k16 mma.sync with a cp.async-fed convert pipeline.
// 128 CTAs = 64 batches x 2 output row-slabs; 256 threads (8 warps):
//   warp w: output tile j=w&1 (cols 64j..64j+63), k-group kg=w>>1 (k16 step kg
//   of each 64-float k-tile), full 64x64 accumulator per warp, combined via
//   SMEM at the end. Pipeline per k-tile: cp.async raw fp32 (2 stages, chunk-
//   XOR swizzle) -> per-thread LDS+cvt+STS into fp16 buffer (2 stages) with
//   exact fp32 row sums -> ldmatrix + MMA. One __syncthreads per k-tile.
// R8 bugfix: convert() now masks the pipeline stage internally (tile & 1);
// R8 passed the raw tile index as a stage index and ran off shared memory.

#define DINLINE __device__ __forceinline__

static constexpr int Bn = 64;
static constexpr int Cn = 128;
static constexpr int Mn = 4096;
static constexpr int KT = 64;               // k floats per tile
static constexpr int NKT = Mn / KT;         // 64
static constexpr int RAW_STAGE = Cn * 256;  // 32768 (256B per row)
static constexpr int FB_ROWB = 144;         // fp16 row: 128B data + 16B pad
static constexpr int FB_STAGE = Cn * FB_ROWB;          // 18432
static constexpr int OFF_RAW = 0;
static constexpr int OFF_FB  = 2 * RAW_STAGE;          // 65536
static constexpr int OFF_MU  = OFF_FB + 2 * FB_STAGE;  // 102400
static constexpr int SMEM_TOTAL = OFF_MU + 512;        // 102912

DINLINE void mma_f16(float d[4], const uint32_t a[4], uint32_t b0, uint32_t b1) {
    asm volatile(
        "mma.sync.aligned.m16n8k16.row.col.f32.f16.f16.f32 "
        "{%0,%1,%2,%3}, {%4,%5,%6,%7}, {%8,%9}, {%0,%1,%2,%3};"
        : "+f"(d[0]), "+f"(d[1]), "+f"(d[2]), "+f"(d[3])
        : "r"(a[0]), "r"(a[1]), "r"(a[2]), "r"(a[3]), "r"(b0), "r"(b1));
}
DINLINE void ldsm_x4(uint32_t r[4], uint32_t addr) {
    asm volatile("ldmatrix.sync.aligned.m8n8.x4.shared.b16 {%0,%1,%2,%3}, [%4];"
                 : "=r"(r[0]), "=r"(r[1]), "=r"(r[2]), "=r"(r[3]) : "r"(addr));
}
DINLINE uint32_t smem_u32(const void* p) {
    uint32_t a;
    asm("{ .reg .u64 t; cvta.to.shared.u64 t, %1; cvt.u32.u64 %0, t; }"
        : "=r"(a) : "l"(p));
    return a;
}
DINLINE void cp16(uint32_t dst, const void* src) {
    asm volatile("cp.async.cg.shared.global [%0], [%1], 16;"
                 :: "r"(dst), "l"(src) : "memory");
}
DINLINE void cp_commit() { asm volatile("cp.async.commit_group;" ::: "memory"); }
template <int N> DINLINE void cp_wait() {
    asm volatile("cp.async.wait_group %0;" :: "n"(N) : "memory");
}

__global__ __launch_bounds__(256, 1)
void covpool_fp16(const float* __restrict__ x, float* __restrict__ y) {
    extern __shared__ char smem[];
    const uint32_t sb = smem_u32(smem);

    const int t    = threadIdx.x;
    const int warp = t >> 5;
    const int lane = t & 31;
    const int s    = blockIdx.x & 1;     // output row-slab
    const int b    = blockIdx.x >> 1;

    // ---- loader / converter mapping: thread owns (row r, half h) ----
    const int r  = t >> 1;
    const int h  = t & 1;
    const int rm = r & 7;
    const float* src = x + (size_t)b * Cn * Mn + (size_t)r * Mn + h * 32;
    uint32_t swo[8];                      // swizzled 16B-chunk offsets in row
#pragma unroll
    for (int j = 0; j < 8; j++)
        swo[j] = (uint32_t)((h * 8 + (j ^ rm)) * 16);
    const uint32_t rawRow = (uint32_t)(OFF_RAW + r * 256);
    const uint32_t fbRow  = (uint32_t)(OFF_FB + r * FB_ROWB + h * 64);

    // ---- MMA geometry ----
    const int jt = warp & 1;              // output col tile
    const int kg = warp >> 1;             // k16 step within k-tile
    const uint32_t kb   = (uint32_t)(kg * 32);
    const uint32_t aoff = (uint32_t)((s * 64 + (lane & 15)) * FB_ROWB
                                     + (lane >> 4) * 16) + kb;
    const uint32_t boff = (uint32_t)((jt * 64 + (lane & 15)) * FB_ROWB
                                     + (lane >> 4) * 16) + kb;
    const int g  = lane >> 2;
    const int tg = lane & 3;

    float acc[4][8][4];
#pragma unroll
    for (int mi = 0; mi < 4; mi++)
#pragma unroll
        for (int ni = 0; ni < 8; ni++)
#pragma unroll
            for (int q = 0; q < 4; q++) acc[mi][ni][q] = 0.0f;

    float rs = 0.0f;

    // convert tile kt_: raw stage (kt_&1) -> fb stage (kt_&1), accumulate row sums
    auto convert = [&](int kt_) {
        const int st = kt_ & 1;           // R8 FIX: stage, not tile, indexes smem
        const uint32_t rb = rawRow + (uint32_t)(st * RAW_STAGE);
        const uint32_t fb = fbRow  + (uint32_t)(st * FB_STAGE);
#pragma unroll
        for (int j = 0; j < 4; j++) {
            float4 v0 = *(const float4*)(smem + rb + swo[2 * j]);
            float4 v1 = *(const float4*)(smem + rb + swo[2 * j + 1]);
            rs += v0.x + v0.y + v0.z + v0.w + v1.x + v1.y + v1.z + v1.w;
            __half2 h0 = __floats2half2_rn(v0.x, v0.y);
            __half2 h1 = __floats2half2_rn(v0.z, v0.w);
            __half2 h2 = __floats2half2_rn(v1.x, v1.y);
            __half2 h3 = __floats2half2_rn(v1.z, v1.w);
            *(uint4*)(smem + fb + j * 16) =
                make_uint4(*(const uint32_t*)&h0, *(const uint32_t*)&h1,
                           *(const uint32_t*)&h2, *(const uint32_t*)&h3);
        }
    };
    auto issue = [&](int kt_) {           // cp.async tile kt_ into raw[kt_&1]
        const uint32_t d0 = sb + rawRow + (uint32_t)((kt_ & 1) * RAW_STAGE);
        const float* sp = src + (size_t)kt_ * KT;
#pragma unroll
        for (int j = 0; j < 8; j++) cp16(d0 + swo[j], sp + j * 4);
    };

    // prologue: tiles 0,1 in flight; convert tile 0
    issue(0); cp_commit();
    issue(1); cp_commit();
    cp_wait<1>();
    convert(0);
    __syncthreads();

    for (int kt = 0; kt < NKT; kt++) {
        if (kt + 2 < NKT) issue(kt + 2);
        cp_commit();
        if (kt + 1 < NKT) {
            if (kt + 2 < NKT) cp_wait<1>(); else cp_wait<0>();
            convert(kt + 1);
        }

        const uint32_t fbb = sb + (uint32_t)(OFF_FB + (kt & 1) * FB_STAGE);
        uint32_t A[4][4], Bf[4][4];
#pragma unroll
        for (int mi = 0; mi < 4; mi++)
            ldsm_x4(A[mi], fbb + aoff + mi * 16 * FB_ROWB);
#pragma unroll
        for (int ni = 0; ni < 4; ni++)
            ldsm_x4(Bf[ni], fbb + boff + ni * 16 * FB_ROWB);
#pragma unroll
        for (int mi = 0; mi < 4; mi++)
#pragma unroll
            for (int ni = 0; ni < 4; ni++) {
                mma_f16(acc[mi][2 * ni],     A[mi], Bf[ni][0], Bf[ni][2]);
                mma_f16(acc[mi][2 * ni + 1], A[mi], Bf[ni][1], Bf[ni][3]);
            }
        __syncthreads();
    }

    // means (exact fp32)
    rs += __shfl_xor_sync(0xffffffffu, rs, 1);
    float* mu = (float*)(smem + OFF_MU);
    if (h == 0) mu[r] = rs * (1.0f / (float)Mn);

    // ---- combine 4 k-group partials per tile (kg 1-3 -> smem, kg 0 reduces) ----
    // scratch region [0, 98304) does not touch mu at 102400
    if (kg > 0) {
        float4* d = (float4*)(smem + ((kg - 1) * 2 + jt) * 16384) + lane;
#pragma unroll
        for (int mi = 0; mi < 4; mi++)
#pragma unroll
            for (int ni = 0; ni < 8; ni++)
                d[(mi * 8 + ni) * 32] = make_float4(acc[mi][ni][0], acc[mi][ni][1],
                                                    acc[mi][ni][2], acc[mi][ni][3]);
    }
    __syncthreads();
    if (kg == 0) {
#pragma unroll
        for (int p = 0; p < 3; p++) {
            const float4* sp = (const float4*)(smem + (p * 2 + jt) * 16384) + lane;
#pragma unroll
            for (int mi = 0; mi < 4; mi++)
#pragma unroll
                for (int ni = 0; ni < 8; ni++) {
                    float4 v = sp[(mi * 8 + ni) * 32];
                    acc[mi][ni][0] += v.x; acc[mi][ni][1] += v.y;
                    acc[mi][ni][2] += v.z; acc[mi][ni][3] += v.w;
                }
        }
        // epilogue: y = acc/M - mu_r * mu_c
        const float a = 1.0f / (float)Mn;
        float* yb = y + (size_t)b * Cn * Cn;
#pragma unroll
        for (int mi = 0; mi < 4; mi++) {
            const int r0 = s * 64 + mi * 16 + g;
            const float mr0 = mu[r0];
            const float mr1 = mu[r0 + 8];
#pragma unroll
            for (int ni = 0; ni < 8; ni++) {
                const int c0 = jt * 64 + ni * 8 + 2 * tg;
                const float mc0 = mu[c0];
                const float mc1 = mu[c0 + 1];
                float2 o0, o1;
                o0.x = acc[mi][ni][0] * a - mr0 * mc0;
                o0.y = acc[mi][ni][1] * a - mr0 * mc1;
                o1.x = acc[mi][ni][2] * a - mr1 * mc0;
                o1.y = acc[mi][ni][3] * a - mr1 * mc1;
                *(float2*)(yb + (size_t)r0 * Cn + c0)       = o0;
                *(float2*)(yb + (size_t)(r0 + 8) * Cn + c0) = o1;
            }
        }
    }
}

extern "C" void kernel_launch(void* const* d_in, const int* in_sizes, int n_in,
                              void* d_out, int out_size) {
    (void)in_sizes; (void)n_in; (void)out_size;
    const float* x = (const float*)d_in[0];
    float* y = (float*)d_out;
    cudaFuncSetAttribute(covpool_fp16,
                         cudaFuncAttributeMaxDynamicSharedMemorySize, SMEM_TOTAL);
    covpool_fp16<<<2 * Bn, 256, SMEM_TOTAL>>>(x, y);
}

// round 10
// speedup vs baseline: 1.4345x; 1.1523x over previous
#include <cuda_runtime.h>
#include <cuda_fp16.h>
#include <cstdint>

// Covariance pooling: y[b] = (1/M) X Xᵀ - μ μᵀ, X = x[b] as [C=128, M=4096].
// Warp-specialized fp16 m16n8k16 pipeline (R9 showed tensor busy only 12% --
// MMAs were starved by convert work sharing the same instruction streams).
// 128 CTAs = 64 batches x 2 output row-slabs; 256 threads:
//   warps 0-3 CONSUMERS: warp (jt=w&1, kg=w>>1) computes output tile jt
//     (cols 64jt..64jt+63) for k16-steps {2kg,2kg+1} of every 64-float k-tile;
//     full private 64x64 accumulator; pure ldsm+MMA stream.
//   warps 4-7 PRODUCERS: one row each; cp.async raw fp32 (2 stages, chunk-XOR
//     swizzle) -> LDS + cvt.rn fp16 + STS into fb (2 stages); exact fp32 row
//     sums in 4 partial accumulators.
// One __syncthreads per k-tile. kg-pair partials combined via SMEM (raw region
// reused); mean subtraction in-kernel; direct stores; no scratch kernel.

#define DINLINE __device__ __forceinline__

static constexpr int Bn = 64;
static constexpr int Cn = 128;
static constexpr int Mn = 4096;
static constexpr int KT = 64;               // k floats per tile
static constexpr int NKT = Mn / KT;         // 64
static constexpr int RAW_STAGE = Cn * 256;  // 32768 (256B per row)
static constexpr int FB_ROWB = 144;         // fp16 row: 128B data + 16B pad
static constexpr int FB_STAGE = Cn * FB_ROWB;          // 18432
static constexpr int OFF_RAW = 0;
static constexpr int OFF_FB  = 2 * RAW_STAGE;          // 65536
static constexpr int OFF_MU  = OFF_FB + 2 * FB_STAGE;  // 102400
static constexpr int SMEM_TOTAL = OFF_MU + 512;        // 102912

DINLINE void mma_f16(float d[4], const uint32_t a[4], uint32_t b0, uint32_t b1) {
    asm volatile(
        "mma.sync.aligned.m16n8k16.row.col.f32.f16.f16.f32 "
        "{%0,%1,%2,%3}, {%4,%5,%6,%7}, {%8,%9}, {%0,%1,%2,%3};"
        : "+f"(d[0]), "+f"(d[1]), "+f"(d[2]), "+f"(d[3])
        : "r"(a[0]), "r"(a[1]), "r"(a[2]), "r"(a[3]), "r"(b0), "r"(b1));
}
DINLINE void ldsm_x4(uint32_t r[4], uint32_t addr) {
    asm volatile("ldmatrix.sync.aligned.m8n8.x4.shared.b16 {%0,%1,%2,%3}, [%4];"
                 : "=r"(r[0]), "=r"(r[1]), "=r"(r[2]), "=r"(r[3]) : "r"(addr));
}
DINLINE uint32_t smem_u32(const void* p) {
    uint32_t a;
    asm("{ .reg .u64 t; cvta.to.shared.u64 t, %1; cvt.u32.u64 %0, t; }"
        : "=r"(a) : "l"(p));
    return a;
}
DINLINE void cp16(uint32_t dst, const void* src) {
    asm volatile("cp.async.cg.shared.global [%0], [%1], 16;"
                 :: "r"(dst), "l"(src) : "memory");
}
DINLINE void cp_commit() { asm volatile("cp.async.commit_group;" ::: "memory"); }
template <int N> DINLINE void cp_wait() {
    asm volatile("cp.async.wait_group %0;" :: "n"(N) : "memory");
}

__global__ __launch_bounds__(256, 1)
void covpool_ws(const float* __restrict__ x, float* __restrict__ y) {
    extern __shared__ char smem[];
    const uint32_t sb = smem_u32(smem);

    const int t    = threadIdx.x;
    const int warp = t >> 5;
    const int lane = t & 31;
    const int s    = blockIdx.x & 1;       // output row-slab
    const int b    = blockIdx.x >> 1;
    const bool producer = (warp >= 4);

    // ---- producer state: one row per thread ----
    const int rr = t & 127;                // row 0..127 (valid for producers)
    const float* src = x + (size_t)b * Cn * Mn + (size_t)rr * Mn;
    uint32_t swo[16];                       // swizzled 16B-chunk offsets in 256B row
#pragma unroll
    for (int j = 0; j < 16; j++)
        swo[j] = (uint32_t)((j ^ (rr & 7)) * 16);
    const uint32_t rawRow = (uint32_t)(OFF_RAW + rr * 256);
    const uint32_t fbRow  = (uint32_t)(OFF_FB + rr * FB_ROWB);

    // ---- consumer state ----
    const int jt = warp & 1;
    const int kg = warp >> 1;              // 0..1 (for warps 0..3)
    const uint32_t aoff = (uint32_t)((s * 64 + (lane & 15)) * FB_ROWB
                                     + (lane >> 4) * 16);
    const uint32_t boff = (uint32_t)((jt * 64 + (lane & 15)) * FB_ROWB
                                     + (lane >> 4) * 16);
    const int g  = lane >> 2;
    const int tg = lane & 3;

    float acc[4][8][4];
#pragma unroll
    for (int mi = 0; mi < 4; mi++)
#pragma unroll
        for (int ni = 0; ni < 8; ni++)
#pragma unroll
            for (int q = 0; q < 4; q++) acc[mi][ni][q] = 0.0f;

    float rs4[4] = {0.0f, 0.0f, 0.0f, 0.0f};

    auto issue = [&](int kt_) {            // cp.async tile kt_ into raw[kt_&1]
        const uint32_t d0 = sb + rawRow + (uint32_t)((kt_ & 1) * RAW_STAGE);
        const float* sp = src + (size_t)kt_ * KT;
#pragma unroll
        for (int j = 0; j < 16; j++) cp16(d0 + swo[j], sp + j * 4);
    };
    auto convert = [&](int kt_) {          // raw[st] -> fb[st], + row sums
        const int st = kt_ & 1;
        const char* rb = smem + rawRow + st * RAW_STAGE;
        char* fb = smem + fbRow + st * FB_STAGE;
#pragma unroll
        for (int j = 0; j < 8; j++) {
            float4 v0 = *(const float4*)(rb + swo[2 * j]);
            float4 v1 = *(const float4*)(rb + swo[2 * j + 1]);
            rs4[j & 3] += (v0.x + v0.y) + (v0.z + v0.w)
                        + (v1.x + v1.y) + (v1.z + v1.w);
            __half2 h0 = __floats2half2_rn(v0.x, v0.y);
            __half2 h1 = __floats2half2_rn(v0.z, v0.w);
            __half2 h2 = __floats2half2_rn(v1.x, v1.y);
            __half2 h3 = __floats2half2_rn(v1.z, v1.w);
            *(uint4*)(fb + j * 16) =
                make_uint4(*(const uint32_t*)&h0, *(const uint32_t*)&h1,
                           *(const uint32_t*)&h2, *(const uint32_t*)&h3);
        }
    };

    // prologue
    if (producer) {
        issue(0); cp_commit();
        issue(1); cp_commit();
        cp_wait<1>();
        convert(0);
    }
    __syncthreads();

    for (int kt = 0; kt < NKT; kt++) {
        if (producer) {
            if (kt + 2 < NKT) { issue(kt + 2); cp_commit(); }
            if (kt + 1 < NKT) {
                if (kt + 2 < NKT) cp_wait<1>(); else cp_wait<0>();
                convert(kt + 1);
            }
        } else {
            const uint32_t fbb = sb + (uint32_t)(OFF_FB + (kt & 1) * FB_STAGE);
#pragma unroll
            for (int ks = 0; ks < 2; ks++) {
                const uint32_t kb = (uint32_t)((kg * 2 + ks) * 32);
                uint32_t A[4][4], Bf[4][4];
#pragma unroll
                for (int mi = 0; mi < 4; mi++)
                    ldsm_x4(A[mi], fbb + aoff + mi * 16 * FB_ROWB + kb);
#pragma unroll
                for (int ni = 0; ni < 4; ni++)
                    ldsm_x4(Bf[ni], fbb + boff + ni * 16 * FB_ROWB + kb);
#pragma unroll
                for (int mi = 0; mi < 4; mi++)
#pragma unroll
                    for (int ni = 0; ni < 4; ni++) {
                        mma_f16(acc[mi][2 * ni],     A[mi], Bf[ni][0], Bf[ni][2]);
                        mma_f16(acc[mi][2 * ni + 1], A[mi], Bf[ni][1], Bf[ni][3]);
                    }
            }
        }
        __syncthreads();
    }

    // means (exact fp32)
    float* mu = (float*)(smem + OFF_MU);
    if (producer)
        mu[rr] = ((rs4[0] + rs4[1]) + (rs4[2] + rs4[3])) * (1.0f / (float)Mn);
    __syncthreads();

    // combine kg-pairs: kg==1 warps dump into raw region, kg==0 reduce + store
    if (!producer && kg == 1) {
        float4* d = (float4*)(smem + OFF_RAW + jt * 16384) + lane * 32;
#pragma unroll
        for (int mi = 0; mi < 4; mi++)
#pragma unroll
            for (int ni = 0; ni < 8; ni++)
                d[mi * 8 + ni] = make_float4(acc[mi][ni][0], acc[mi][ni][1],
                                             acc[mi][ni][2], acc[mi][ni][3]);
    }
    __syncthreads();
    if (!producer && kg == 0) {
        const float4* sp = (const float4*)(smem + OFF_RAW + jt * 16384) + lane * 32;
#pragma unroll
        for (int mi = 0; mi < 4; mi++)
#pragma unroll
            for (int ni = 0; ni < 8; ni++) {
                float4 v = sp[mi * 8 + ni];
                acc[mi][ni][0] += v.x; acc[mi][ni][1] += v.y;
                acc[mi][ni][2] += v.z; acc[mi][ni][3] += v.w;
            }
        // epilogue: y = acc/M - mu_r * mu_c
        const float a = 1.0f / (float)Mn;
        float* yb = y + (size_t)b * Cn * Cn;
#pragma unroll
        for (int mi = 0; mi < 4; mi++) {
            const int r0 = s * 64 + mi * 16 + g;
            const float mr0 = mu[r0];
            const float mr1 = mu[r0 + 8];
#pragma unroll
            for (int ni = 0; ni < 8; ni++) {
                const int c0 = jt * 64 + ni * 8 + 2 * tg;
                const float mc0 = mu[c0];
                const float mc1 = mu[c0 + 1];
                float2 o0, o1;
                o0.x = acc[mi][ni][0] * a - mr0 * mc0;
                o0.y = acc[mi][ni][1] * a - mr0 * mc1;
                o1.x = acc[mi][ni][2] * a - mr1 * mc0;
                o1.y = acc[mi][ni][3] * a - mr1 * mc1;
                *(float2*)(yb + (size_t)r0 * Cn + c0)       = o0;
                *(float2*)(yb + (size_t)(r0 + 8) * Cn + c0) = o1;
            }
        }
    }
}

extern "C" void kernel_launch(void* const* d_in, const int* in_sizes, int n_in,
                              void* d_out, int out_size) {
    (void)in_sizes; (void)n_in; (void)out_size;
    const float* x = (const float*)d_in[0];
    float* y = (float*)d_out;
    cudaFuncSetAttribute(covpool_ws,
                         cudaFuncAttributeMaxDynamicSharedMemorySize, SMEM_TOTAL);
    covpool_ws<<<2 * Bn, 256, SMEM_TOTAL>>>(x, y);
}

// round 11
// speedup vs baseline: 1.8395x; 1.2823x over previous
#include <cuda_runtime.h>
#include <cstdint>

// Covariance pooling: y[b] = (1/M) X Xᵀ - μ μᵀ, X = x[b] as [C=128, M=4096].
// tf32 mma.sync SYRK with in-CTA symmetry (y symmetric -> 3 of 4 64x64 tiles).
// Kernel 1 (partial): 128 CTAs = 64 batches x 2 K-halves, 256 threads (8 warps).
//   Warp map (warp w -> SMSP w&3), balanced at 96 MMA/SMSP/k-tile (= 0.75x R4):
//     w0/w1: tile(0,0) k8-steps {0,1}/{2,3}   w2/w3: tile(1,1) same split
//     w4..w7: tile(0,1), one k8-step each
//   cp.async 4-stage pipeline; raw-fp32 into tf32 MMA (debias CORR); exact fp32
//   row sums in-pipeline. Partials combined via SMEM, 3 tiles to scratch.
// Kernel 2 (finish): 256 CTAs; combines K-halves, applies mean subtraction,
//   mirrors the off-diagonal tile into the lower triangle.

#define DINLINE __device__ __forceinline__

static constexpr int Bn = 64;
static constexpr int Cn = 128;
static constexpr int Mn = 4096;
static constexpr int KHALF = Mn / 2;       // 2048
static constexpr int KT = 32;              // k floats per tile
static constexpr int NKT = KHALF / KT;     // 64
static constexpr int PADB = 144;           // bytes per SMEM row (36 floats)
static constexpr int STAGES = 4;
static constexpr int STAGE_B = Cn * PADB;  // 18432
static constexpr int SMEM_B = STAGES * STAGE_B;  // 73728 (covers 48KB combine too)

// tf32 truncation debias: 1/(1 - 2 * 2^-11 * (1/(2 ln 2)))
static constexpr float CORR = 1.00070466f;

__device__ float g_part[2 * Bn][3][64 * 64];   // [cta][0=d00,1=d11,2=off01]
__device__ float g_sums[2 * Bn][Cn];

DINLINE void mma_tf32(float d[4], const uint32_t a[4], uint32_t b0, uint32_t b1) {
    asm volatile(
        "mma.sync.aligned.m16n8k8.row.col.f32.tf32.tf32.f32 "
        "{%0,%1,%2,%3}, {%4,%5,%6,%7}, {%8,%9}, {%0,%1,%2,%3};"
        : "+f"(d[0]), "+f"(d[1]), "+f"(d[2]), "+f"(d[3])
        : "r"(a[0]), "r"(a[1]), "r"(a[2]), "r"(a[3]), "r"(b0), "r"(b1));
}
DINLINE void ldsm_x4(uint32_t r[4], uint32_t addr) {
    asm volatile("ldmatrix.sync.aligned.m8n8.x4.shared.b16 {%0,%1,%2,%3}, [%4];"
                 : "=r"(r[0]), "=r"(r[1]), "=r"(r[2]), "=r"(r[3]) : "r"(addr));
}
DINLINE uint32_t smem_u32(const void* p) {
    uint32_t a;
    asm("{ .reg .u64 t; cvta.to.shared.u64 t, %1; cvt.u32.u64 %0, t; }"
        : "=r"(a) : "l"(p));
    return a;
}
DINLINE void cp16(uint32_t dst, const void* src) {
    asm volatile("cp.async.cg.shared.global [%0], [%1], 16;"
                 :: "r"(dst), "l"(src) : "memory");
}
DINLINE void cp_commit() { asm volatile("cp.async.commit_group;" ::: "memory"); }
template <int N> DINLINE void cp_wait() {
    asm volatile("cp.async.wait_group %0;" :: "n"(N) : "memory");
}

__global__ __launch_bounds__(256, 1)
void covpool_partial(const float* __restrict__ x) {
    extern __shared__ char smem[];
    const uint32_t sb = smem_u32(smem);

    const int t    = threadIdx.x;
    const int warp = t >> 5;
    const int lane = t & 31;
    const int cta  = blockIdx.x;        // 0..127
    const int s    = cta & 1;
    const int b    = cta >> 1;

    // loader: 2 threads per row, 64B each per k-tile
    const int lrow = t >> 1;
    const int lh   = t & 1;
    const float* xsrc = x + (size_t)b * Cn * Mn + (size_t)lrow * Mn
                          + (size_t)s * KHALF + lh * 16;
    const uint32_t ldst = (uint32_t)(lrow * PADB + lh * 64);

    // warp job: tile (wm, wn) + k8-step set {ks0 .. ks0+nks-1}
    int wm, wn, ks0;
    bool two_steps;
    if (warp < 4) {
        wm = (warp >> 1) * 64; wn = wm;          // diag tiles
        ks0 = (warp & 1) * 2;  two_steps = true;
    } else {
        wm = 0; wn = 64;                          // off-diag tile
        ks0 = warp - 4;        two_steps = false;
    }

    // ldmatrix lane offsets (R4-proven formulas)
    const uint32_t aoff = (uint32_t)((wm + (lane & 15)) * PADB + (lane >> 4) * 16);
    const uint32_t boff = (uint32_t)((wn + (lane & 7) + ((lane >> 4) * 8)) * PADB
                                     + ((lane >> 3) & 1) * 16);
    const int g  = lane >> 2;
    const int tg = lane & 3;

    float acc[4][8][4];
#pragma unroll
    for (int im = 0; im < 4; im++)
#pragma unroll
        for (int in = 0; in < 8; in++)
#pragma unroll
            for (int j = 0; j < 4; j++) acc[im][in][j] = 0.0f;

    float rowsum = 0.0f;

    // prologue: stages 0..2
#pragma unroll
    for (int p = 0; p < STAGES - 1; p++) {
        const uint32_t d0 = sb + p * STAGE_B + ldst;
        const float* src = xsrc + p * KT;
#pragma unroll
        for (int i = 0; i < 4; i++) cp16(d0 + i * 16, src + i * 4);
        cp_commit();
    }

    for (int kt = 0; kt < NKT; kt++) {
        cp_wait<STAGES - 2>();
        __syncthreads();
        if (kt + STAGES - 1 < NKT) {
            const uint32_t d0 = sb + ((kt + STAGES - 1) & (STAGES - 1)) * STAGE_B + ldst;
            const float* src = xsrc + (kt + STAGES - 1) * KT;
#pragma unroll
            for (int i = 0; i < 4; i++) cp16(d0 + i * 16, src + i * 4);
        }
        cp_commit();

        const uint32_t base = sb + (kt & (STAGES - 1)) * STAGE_B;

        // exact fp32 row sum of this thread's own half row
#pragma unroll
        for (int i = 0; i < 4; i++) {
            float4 v = *(const float4*)(smem + (kt & (STAGES - 1)) * STAGE_B
                                        + lrow * PADB + lh * 64 + i * 16);
            rowsum += v.x + v.y + v.z + v.w;
        }

        auto mma_step = [&](uint32_t k0) {
            uint32_t A[4][4], Bf[4][4];
#pragma unroll
            for (int im = 0; im < 4; im++)
                ldsm_x4(A[im], base + aoff + im * 16 * PADB + k0);
#pragma unroll
            for (int jn = 0; jn < 4; jn++)
                ldsm_x4(Bf[jn], base + boff + jn * 16 * PADB + k0);
#pragma unroll
            for (int im = 0; im < 4; im++)
#pragma unroll
                for (int jn = 0; jn < 4; jn++) {
                    mma_tf32(acc[im][2 * jn],     A[im], Bf[jn][0], Bf[jn][1]);
                    mma_tf32(acc[im][2 * jn + 1], A[im], Bf[jn][2], Bf[jn][3]);
                }
        };
        const uint32_t kb0 = (uint32_t)(ks0 * 32);
        if (two_steps) { mma_step(kb0); mma_step(kb0 + 32); }
        else           { mma_step(kb0); }
    }

    // row sums (pairs of threads share a row)
    rowsum += __shfl_xor_sync(0xffffffffu, rowsum, 1);
    if (lh == 0) g_sums[cta][lrow] = rowsum;

    // ---- combine warp partials: phase 1 (w1,w3,w5 dump; w0,w2,w4 reduce) ----
    __syncthreads();
    float* cs = (float*)smem;
    auto dump = [&](int region) {
        float4* d = (float4*)(cs + (size_t)region * 4096) + lane * 32;
#pragma unroll
        for (int im = 0; im < 4; im++)
#pragma unroll
            for (int in = 0; in < 8; in++)
                d[im * 8 + in] = make_float4(acc[im][in][0], acc[im][in][1],
                                             acc[im][in][2], acc[im][in][3]);
    };
    auto reduce = [&](int region) {
        const float4* sp = (const float4*)(cs + (size_t)region * 4096) + lane * 32;
#pragma unroll
        for (int im = 0; im < 4; im++)
#pragma unroll
            for (int in = 0; in < 8; in++) {
                float4 v = sp[im * 8 + in];
                acc[im][in][0] += v.x; acc[im][in][1] += v.y;
                acc[im][in][2] += v.z; acc[im][in][3] += v.w;
            }
    };

    if (warp == 1) dump(0);
    else if (warp == 3) dump(1);
    else if (warp == 5) dump(2);
    __syncthreads();
    if (warp == 0) reduce(0);
    else if (warp == 2) reduce(1);
    else if (warp == 4) reduce(2);
    __syncthreads();
    if (warp == 6) dump(0);
    else if (warp == 7) dump(1);
    __syncthreads();
    if (warp == 4) { reduce(0); reduce(1); }

    // stores: w0 -> tile0 (d00), w2 -> tile1 (d11), w4 -> tile2 (off01)
    if (warp == 0 || warp == 2 || warp == 4) {
        const int tileIdx = (warp == 0) ? 0 : (warp == 2) ? 1 : 2;
        float* gp = g_part[cta][tileIdx];
#pragma unroll
        for (int im = 0; im < 4; im++) {
            const int r0 = im * 16 + g;
#pragma unroll
            for (int in = 0; in < 8; in++) {
                const int c0 = in * 8 + 2 * tg;
                *(float2*)(gp + r0 * 64 + c0) =
                    make_float2(acc[im][in][0], acc[im][in][1]);
                *(float2*)(gp + (r0 + 8) * 64 + c0) =
                    make_float2(acc[im][in][2], acc[im][in][3]);
            }
        }
    }
}

__global__ __launch_bounds__(256, 2)
void covpool_finish(float* __restrict__ y) {
    __shared__ float mu[Cn];
    const int t = threadIdx.x;
    const int b = blockIdx.x >> 2;
    const int q = blockIdx.x & 3;
    if (t < Cn)
        mu[t] = (g_sums[2 * b][t] + g_sums[2 * b + 1][t]) * (1.0f / (float)Mn);
    __syncthreads();

    const float a = CORR * (1.0f / (float)Mn);
    float* yb = y + (size_t)b * Cn * Cn;

    if (q == 0 || q == 3) {                 // diagonal quadrants
        const int d = (q == 0) ? 0 : 64;
        const int ti = (q == 0) ? 0 : 1;
        const float4* G0 = (const float4*)g_part[2 * b][ti];
        const float4* G1 = (const float4*)g_part[2 * b + 1][ti];
#pragma unroll
        for (int k = 0; k < 4; k++) {
            const int e4 = t + k * 256;     // float4 idx in [0,1024)
            const int i  = e4 >> 4;
            const int j4 = e4 & 15;
            float4 p0 = G0[e4], p1 = G1[e4];
            const float mr = mu[d + i];
            const float4 m = ((const float4*)mu)[(d >> 2) + j4];
            float4 o;
            o.x = (p0.x + p1.x) * a - mr * m.x;
            o.y = (p0.y + p1.y) * a - mr * m.y;
            o.z = (p0.z + p1.z) * a - mr * m.z;
            o.w = (p0.w + p1.w) * a - mr * m.w;
            ((float4*)(yb + (size_t)(d + i) * Cn + d))[j4] = o;
        }
    } else if (q == 1) {                    // upper-right: rows 0-63, cols 64-127
        const float4* G0 = (const float4*)g_part[2 * b][2];
        const float4* G1 = (const float4*)g_part[2 * b + 1][2];
#pragma unroll
        for (int k = 0; k < 4; k++) {
            const int e4 = t + k * 256;
            const int i  = e4 >> 4;
            const int j4 = e4 & 15;
            float4 p0 = G0[e4], p1 = G1[e4];
            const float mr = mu[i];
            const float4 m = ((const float4*)mu)[16 + j4];
            float4 o;
            o.x = (p0.x + p1.x) * a - mr * m.x;
            o.y = (p0.y + p1.y) * a - mr * m.y;
            o.z = (p0.z + p1.z) * a - mr * m.z;
            o.w = (p0.w + p1.w) * a - mr * m.w;
            ((float4*)(yb + (size_t)i * Cn + 64))[j4] = o;
        }
    } else {                                // lower-left: transposed off-diag
        const float* Ga = g_part[2 * b][2];
        const float* Gb = g_part[2 * b + 1][2];
#pragma unroll
        for (int k = 0; k < 4; k++) {
            const int e4 = t + k * 256;
            const int jj = e4 >> 4;          // out row 64+jj
            const int i0 = (e4 & 15) * 4;    // out cols i0..i0+3
            const float mr = mu[64 + jj];
            float4 o;
            o.x = (Ga[(i0 + 0) * 64 + jj] + Gb[(i0 + 0) * 64 + jj]) * a - mr * mu[i0 + 0];
            o.y = (Ga[(i0 + 1) * 64 + jj] + Gb[(i0 + 1) * 64 + jj]) * a - mr * mu[i0 + 1];
            o.z = (Ga[(i0 + 2) * 64 + jj] + Gb[(i0 + 2) * 64 + jj]) * a - mr * mu[i0 + 2];
            o.w = (Ga[(i0 + 3) * 64 + jj] + Gb[(i0 + 3) * 64 + jj]) * a - mr * mu[i0 + 3];
            *(float4*)(yb + (size_t)(64 + jj) * Cn + i0) = o;
        }
    }
}

extern "C" void kernel_launch(void* const* d_in, const int* in_sizes, int n_in,
                              void* d_out, int out_size) {
    (void)in_sizes; (void)n_in; (void)out_size;
    const float* x = (const float*)d_in[0];
    float* y = (float*)d_out;
    cudaFuncSetAttribute(covpool_partial,
                         cudaFuncAttributeMaxDynamicSharedMemorySize, SMEM_B);
    covpool_partial<<<2 * Bn, 256, SMEM_B>>>(x);
    covpool_finish<<<4 * Bn, 256>>>(y);
}